// round 12
// baseline (speedup 1.0000x reference)
#include <cuda_runtime.h>
#include <cuda_fp16.h>
#include <stdint.h>

#define D_MODEL 1024
#define NHEAD   16
#define DH      64
#define SEQ     2048
#define BATCH   4
#define MTOT    8192
#define KE      2048

// ---------------- scratch globals (no allocation) ----------------
__device__ __half g_Xe[(size_t)MTOT*KE];                 // X hi|lo
__device__ __half g_Te[(size_t)MTOT*KE];                 // attn out hi|lo
__device__ __half g_W[4][(size_t)D_MODEL*D_MODEL];       // weights fp16
__device__ __half g_Qh[(size_t)BATCH*NHEAD*SEQ*DH];      // [B,H,S,64]
__device__ __half g_Kh[(size_t)BATCH*NHEAD*SEQ*DH];
__device__ __half g_Vh[(size_t)BATCH*NHEAD*SEQ*DH];

// ---------------- helpers ----------------
__device__ __forceinline__ uint32_t smem_u32(const void* p) {
    uint32_t a;
    asm("{ .reg .u64 t; cvta.to.shared.u64 t, %1; cvt.u32.u64 %0, t; }" : "=r"(a) : "l"(p));
    return a;
}
__device__ __forceinline__ void cp16(uint32_t s, const void* g) {
    asm volatile("cp.async.cg.shared.global [%0], [%1], 16;" :: "r"(s), "l"(g));
}
#define CP_COMMIT() asm volatile("cp.async.commit_group;" ::: "memory")
#define CP_WAIT(n)  asm volatile("cp.async.wait_group %0;" :: "n"(n) : "memory")

__device__ __forceinline__ void ldsm(uint32_t& r0, uint32_t& r1, uint32_t& r2, uint32_t& r3, uint32_t a) {
    asm volatile("ldmatrix.sync.aligned.m8n8.x4.shared.b16 {%0,%1,%2,%3}, [%4];"
                 : "=r"(r0), "=r"(r1), "=r"(r2), "=r"(r3) : "r"(a));
}
__device__ __forceinline__ void ldsmT(uint32_t& r0, uint32_t& r1, uint32_t& r2, uint32_t& r3, uint32_t a) {
    asm volatile("ldmatrix.sync.aligned.m8n8.x4.trans.shared.b16 {%0,%1,%2,%3}, [%4];"
                 : "=r"(r0), "=r"(r1), "=r"(r2), "=r"(r3) : "r"(a));
}
__device__ __forceinline__ void mma16(float* c, uint32_t a0, uint32_t a1, uint32_t a2, uint32_t a3,
                                      uint32_t b0, uint32_t b1) {
    asm volatile("mma.sync.aligned.m16n8k16.row.col.f32.f16.f16.f32 "
                 "{%0,%1,%2,%3}, {%4,%5,%6,%7}, {%8,%9}, {%0,%1,%2,%3};"
                 : "+f"(c[0]), "+f"(c[1]), "+f"(c[2]), "+f"(c[3])
                 : "r"(a0), "r"(a1), "r"(a2), "r"(a3), "r"(b0), "r"(b1));
}
#define SWZ(x) ((uint32_t)(x) ^ ((((uint32_t)(x)) >> 3) & 0x70))

__device__ __forceinline__ uint32_t packh2(float a, float b) {
    __half2 h = __floats2half2_rn(a, b);
    return *reinterpret_cast<uint32_t*>(&h);
}

// ---------------- converters (vectorized) ----------------
__global__ void conv_x(const float4* __restrict__ s) {
    const int N4 = MTOT * D_MODEL / 4;
    for (int i = blockIdx.x * blockDim.x + threadIdx.x; i < N4; i += gridDim.x * blockDim.x) {
        float4 v = s[i];
        int e = i * 4, r = e >> 10, c = e & 1023;
        __half2 h0 = __floats2half2_rn(v.x, v.y);
        __half2 h1 = __floats2half2_rn(v.z, v.w);
        __half2 l0 = __floats2half2_rn(v.x - __half2float(__low2half(h0)),
                                       v.y - __half2float(__high2half(h0)));
        __half2 l1 = __floats2half2_rn(v.z - __half2float(__low2half(h1)),
                                       v.w - __half2float(__high2half(h1)));
        __half* base = g_Xe + (size_t)r * KE + c;
        *(__half2*)(base)          = h0;
        *(__half2*)(base + 2)      = h1;
        *(__half2*)(base + 1024)   = l0;
        *(__half2*)(base + 1026)   = l1;
    }
}
__global__ void conv_w4(const float4* __restrict__ w0, const float4* __restrict__ w1,
                        const float4* __restrict__ w2, const float4* __restrict__ w3) {
    const int N4 = D_MODEL * D_MODEL / 4;
    for (int i = blockIdx.x * blockDim.x + threadIdx.x; i < 4 * N4; i += gridDim.x * blockDim.x) {
        int m = i >> 18, idx = i & (N4 - 1);
        const float4* s = (m == 0) ? w0 : (m == 1) ? w1 : (m == 2) ? w2 : w3;
        float4 v = s[idx];
        __half2 h0 = __floats2half2_rn(v.x, v.y);
        __half2 h1 = __floats2half2_rn(v.z, v.w);
        *(__half2*)(g_W[m] + idx * 4)     = h0;
        *(__half2*)(g_W[m] + idx * 4 + 2) = h1;
    }
}

// ---------------- 2-pass fp16 GEMM: C = (Ah+Al) * W^T ----------------
// 128x256 block tile, 8 warps (2m x 4n) of 64x64; 16 K-chunks of 64.
// 3-stage pipeline, ONE __syncthreads per chunk. Stage = Ah(16K)|Al(16K)|B(32K) = 64KB.
// mode_base < 0: mode = blockIdx.z (0/1/2 -> Qh/Kh/Vh); mode_base == 3: WO -> outp fp32.
#define GST2 65536
#define GSM3 (3 * GST2)     // 196608
__global__ __launch_bounds__(256) void gemm_h(float* __restrict__ outp, int mode_base)
{
    extern __shared__ char smem[];
    uint32_t sb = smem_u32(smem);
    int mode = (mode_base < 0) ? (int)blockIdx.z : mode_base;
    int tid = threadIdx.x, lid = tid & 31, wid = tid >> 5;
    int wm = wid >> 2, wn = wid & 3;
    int m0 = blockIdx.y * 128, n0 = blockIdx.x * 256;

    const __half* A = (mode == 3) ? g_Te : g_Xe;
    const char* Ab = (const char*)(A + (size_t)m0 * KE);
    const char* Bb = (const char*)(g_W[mode] + (size_t)n0 * D_MODEL);

    float acc[4][8][4];
#pragma unroll
    for (int mt = 0; mt < 4; ++mt)
#pragma unroll
        for (int j = 0; j < 8; ++j)
#pragma unroll
            for (int v = 0; v < 4; ++v) acc[mt][j][v] = 0.f;

    auto LD = [&](int c, uint32_t st) {
#pragma unroll
        for (int t = 0; t < 4; ++t) {          // A hi + lo: 128 rows x 128B each
            int idx = tid + t * 256, row = idx >> 3, cc = (idx & 7) * 16;
            uint32_t so = SWZ(row * 128 + cc);
            cp16(st + so,         Ab + (size_t)row * 4096 + c * 128 + cc);
            cp16(st + 16384 + so, Ab + (size_t)row * 4096 + 2048 + c * 128 + cc);
        }
#pragma unroll
        for (int t = 0; t < 8; ++t) {          // B: 256 rows x 128B
            int idx = tid + t * 256, row = idx >> 3, cc = (idx & 7) * 16;
            uint32_t so = SWZ(row * 128 + cc);
            cp16(st + 32768 + so, Bb + (size_t)row * 2048 + c * 128 + cc);
        }
    };

    LD(0, sb); CP_COMMIT();
    LD(1, sb + GST2); CP_COMMIT();

    for (int i = 0; i < 16; ++i) {
        CP_WAIT(1);
        __syncthreads();
        if (i + 2 < 16) LD(i + 2, sb + ((i + 2) % 3) * GST2);
        CP_COMMIT();

        uint32_t st = sb + (i % 3) * GST2;
#pragma unroll
        for (int ks = 0; ks < 4; ++ks) {
            int kb = ks * 32;
            uint32_t ah[4][4], al[4][4];
#pragma unroll
            for (int mt = 0; mt < 4; ++mt) {
                uint32_t off = SWZ((wm * 64 + mt * 16 + (lid & 15)) * 128 + kb + (lid >> 4) * 16);
                ldsm(ah[mt][0], ah[mt][1], ah[mt][2], ah[mt][3], st + off);
                ldsm(al[mt][0], al[mt][1], al[mt][2], al[mt][3], st + 16384 + off);
            }
#pragma unroll
            for (int ng = 0; ng < 4; ++ng) {
                uint32_t boff = SWZ((wn * 64 + ng * 16 + ((lid >> 4) << 3) + (lid & 7)) * 128
                                    + kb + ((lid >> 3) & 1) * 16);
                uint32_t b0, b1, b2, b3;
                ldsm(b0, b1, b2, b3, st + 32768 + boff);
#pragma unroll
                for (int mt = 0; mt < 4; ++mt) {
                    mma16(acc[mt][ng * 2],     ah[mt][0], ah[mt][1], ah[mt][2], ah[mt][3], b0, b1);
                    mma16(acc[mt][ng * 2 + 1], ah[mt][0], ah[mt][1], ah[mt][2], ah[mt][3], b2, b3);
                    mma16(acc[mt][ng * 2],     al[mt][0], al[mt][1], al[mt][2], al[mt][3], b0, b1);
                    mma16(acc[mt][ng * 2 + 1], al[mt][0], al[mt][1], al[mt][2], al[mt][3], b2, b3);
                }
            }
        }
        __syncthreads();   // all warps done with stage i before it is reloaded (i+3)
    }

#pragma unroll
    for (int mt = 0; mt < 4; ++mt)
#pragma unroll
        for (int j = 0; j < 8; ++j) {
            int row = m0 + wm * 64 + mt * 16 + (lid >> 2);
            int col = n0 + wn * 64 + j * 8 + ((lid & 3) << 1);
            if (mode == 3) {
                *(float2*)(outp + (size_t)row * D_MODEL + col)       = make_float2(acc[mt][j][0], acc[mt][j][1]);
                *(float2*)(outp + (size_t)(row + 8) * D_MODEL + col) = make_float2(acc[mt][j][2], acc[mt][j][3]);
            } else {
                __half* dst = (mode == 0) ? g_Qh : (mode == 1) ? g_Kh : g_Vh;
                int h = col >> 6, d = col & 63;
                int b0_ = row >> 11, s0 = row & 2047, r1 = row + 8, b1_ = r1 >> 11, s1 = r1 & 2047;
                *(__half2*)(dst + (((size_t)(b0_ * NHEAD + h) * SEQ + s0)) * DH + d)
                    = __floats2half2_rn(acc[mt][j][0], acc[mt][j][1]);
                *(__half2*)(dst + (((size_t)(b1_ * NHEAD + h) * SEQ + s1)) * DH + d)
                    = __floats2half2_rn(acc[mt][j][2], acc[mt][j][3]);
            }
        }
}

// ---------------- fp16 tensor-core flash attention (unchanged, known-good) ----------------
#define ATT_SMEM 49152   // Q 16K | K0 8K | V0 8K | K1 8K | V1 8K
__global__ __launch_bounds__(256) void attn_h()
{
    extern __shared__ char smem[];
    uint32_t sb = smem_u32(smem);
    uint32_t Qs = sb;
    uint32_t Ks[2] = {sb + 16384, sb + 32768};
    uint32_t Vs[2] = {sb + 24576, sb + 40960};

    int tid = threadIdx.x, lid = tid & 31, w = tid >> 5;
    int qb = (int)gridDim.x - 1 - (int)blockIdx.x;
    int bh = blockIdx.y;

    const char* Qg = (const char*)(g_Qh + ((size_t)bh * SEQ + qb * 128) * DH);
    const char* Kg = (const char*)(g_Kh + (size_t)bh * SEQ * DH);
    const char* Vg = (const char*)(g_Vh + (size_t)bh * SEQ * DH);

    auto loadKV = [&](int kt, int buf) {
#pragma unroll
        for (int t = 0; t < 2; ++t) {
            int idx = tid + t * 256, row = idx >> 3, c = (idx & 7) * 16;
            uint32_t so = SWZ(row * 128 + c);
            cp16(Ks[buf] + so, Kg + (size_t)(kt * 64 + row) * 128 + c);
            cp16(Vs[buf] + so, Vg + (size_t)(kt * 64 + row) * 128 + c);
        }
    };

#pragma unroll
    for (int t = 0; t < 4; ++t) {
        int idx = tid + t * 256, row = idx >> 3, c = (idx & 7) * 16;
        cp16(Qs + SWZ(row * 128 + c), Qg + (size_t)row * 128 + c);
    }
    CP_COMMIT();
    loadKV(0, 0); CP_COMMIT();
    CP_WAIT(0); __syncthreads();

    uint32_t qf[4][4];
#pragma unroll
    for (int ks = 0; ks < 4; ++ks) {
        uint32_t off = SWZ((w * 16 + (lid & 15)) * 128 + ks * 32 + (lid >> 4) * 16);
        ldsm(qf[ks][0], qf[ks][1], qf[ks][2], qf[ks][3], Qs + off);
    }

    float o[8][4];
#pragma unroll
    for (int j = 0; j < 8; ++j)
#pragma unroll
        for (int v = 0; v < 4; ++v) o[j][v] = 0.f;
    float m0 = -1e30f, m1 = -1e30f, l0 = 0.f, l1 = 0.f;

    int r0 = lid >> 2, c0 = (lid & 3) << 1;
    int qlo = qb * 128 + w * 16;
    int ntiles = 2 * qb + 2;

    for (int kt = 0; kt < ntiles; ++kt) {
        int buf = kt & 1;
        if (kt + 1 < ntiles) { loadKV(kt + 1, buf ^ 1); CP_COMMIT(); CP_WAIT(1); }
        else CP_WAIT(0);
        __syncthreads();

        if (kt * 64 <= qlo + 15) {
            float s[8][4];
#pragma unroll
            for (int j = 0; j < 8; ++j)
#pragma unroll
                for (int v = 0; v < 4; ++v) s[j][v] = 0.f;
#pragma unroll
            for (int ks = 0; ks < 4; ++ks) {
                int kb = ks * 32;
#pragma unroll
                for (int ng = 0; ng < 4; ++ng) {
                    uint32_t boff = SWZ((ng * 16 + ((lid >> 4) << 3) + (lid & 7)) * 128
                                        + kb + ((lid >> 3) & 1) * 16);
                    uint32_t b0, b1, b2, b3;
                    ldsm(b0, b1, b2, b3, Ks[buf] + boff);
                    mma16(s[ng * 2],     qf[ks][0], qf[ks][1], qf[ks][2], qf[ks][3], b0, b1);
                    mma16(s[ng * 2 + 1], qf[ks][0], qf[ks][1], qf[ks][2], qf[ks][3], b2, b3);
                }
            }
            bool diag = (kt * 64 + 63 > qlo);
#pragma unroll
            for (int j = 0; j < 8; ++j)
#pragma unroll
                for (int v = 0; v < 4; ++v) {
                    float val = s[j][v] * 0.125f;
                    if (diag) {
                        int key = kt * 64 + j * 8 + c0 + (v & 1);
                        int q = qlo + r0 + ((v >> 1) << 3);
                        if (key > q) val = -1e30f;
                    }
                    s[j][v] = val;
                }
            float mt0 = -1e30f, mt1 = -1e30f;
#pragma unroll
            for (int j = 0; j < 8; ++j) {
                mt0 = fmaxf(mt0, fmaxf(s[j][0], s[j][1]));
                mt1 = fmaxf(mt1, fmaxf(s[j][2], s[j][3]));
            }
            mt0 = fmaxf(mt0, __shfl_xor_sync(0xffffffffu, mt0, 1));
            mt0 = fmaxf(mt0, __shfl_xor_sync(0xffffffffu, mt0, 2));
            mt1 = fmaxf(mt1, __shfl_xor_sync(0xffffffffu, mt1, 1));
            mt1 = fmaxf(mt1, __shfl_xor_sync(0xffffffffu, mt1, 2));
            float mn0 = fmaxf(m0, mt0), mn1 = fmaxf(m1, mt1);
            float a0 = __expf(m0 - mn0), a1 = __expf(m1 - mn1);
            m0 = mn0; m1 = mn1;
            float ls0 = 0.f, ls1 = 0.f;
            uint32_t pa[8], pb[8];
#pragma unroll
            for (int j = 0; j < 8; ++j) {
                float p00 = __expf(s[j][0] - mn0), p01 = __expf(s[j][1] - mn0);
                float p10 = __expf(s[j][2] - mn1), p11 = __expf(s[j][3] - mn1);
                ls0 += p00 + p01; ls1 += p10 + p11;
                pa[j] = packh2(p00, p01);
                pb[j] = packh2(p10, p11);
            }
            ls0 += __shfl_xor_sync(0xffffffffu, ls0, 1);
            ls0 += __shfl_xor_sync(0xffffffffu, ls0, 2);
            ls1 += __shfl_xor_sync(0xffffffffu, ls1, 1);
            ls1 += __shfl_xor_sync(0xffffffffu, ls1, 2);
            l0 = l0 * a0 + ls0; l1 = l1 * a1 + ls1;
#pragma unroll
            for (int j = 0; j < 8; ++j) {
                o[j][0] *= a0; o[j][1] *= a0; o[j][2] *= a1; o[j][3] *= a1;
            }
#pragma unroll
            for (int ks2 = 0; ks2 < 4; ++ks2) {
                uint32_t A0 = pa[2 * ks2], A1 = pb[2 * ks2], A2 = pa[2 * ks2 + 1], A3 = pb[2 * ks2 + 1];
#pragma unroll
                for (int ng = 0; ng < 4; ++ng) {
                    uint32_t voff = SWZ((ks2 * 16 + ((lid >> 3) & 1) * 8 + (lid & 7)) * 128
                                        + ng * 32 + (lid >> 4) * 16);
                    uint32_t b0, b1, b2, b3;
                    ldsmT(b0, b1, b2, b3, Vs[buf] + voff);
                    mma16(o[ng * 2],     A0, A1, A2, A3, b0, b1);
                    mma16(o[ng * 2 + 1], A0, A1, A2, A3, b2, b3);
                }
            }
        }
        __syncthreads();
    }

    float il0 = 1.f / l0, il1 = 1.f / l1;
    int b = bh >> 4, h = bh & 15;
    size_t t0 = (size_t)b * SEQ + qb * 128 + w * 16 + r0;
    size_t t1 = t0 + 8;
#pragma unroll
    for (int j = 0; j < 8; ++j) {
        int d = h * 64 + j * 8 + c0;
        float x0 = o[j][0] * il0, x1 = o[j][1] * il0;
        float y0 = o[j][2] * il1, y1 = o[j][3] * il1;
        __half h0 = __float2half_rn(x0), h1 = __float2half_rn(x1);
        __half g0 = __float2half_rn(y0), g1 = __float2half_rn(y1);
        *(__half2*)&g_Te[t0 * KE + d] = __halves2half2(h0, h1);
        *(__half2*)&g_Te[t1 * KE + d] = __halves2half2(g0, g1);
        *(__half2*)&g_Te[t0 * KE + 1024 + d] =
            __floats2half2_rn(x0 - __half2float(h0), x1 - __half2float(h1));
        *(__half2*)&g_Te[t1 * KE + 1024 + d] =
            __floats2half2_rn(y0 - __half2float(g0), y1 - __half2float(g1));
    }
}

// ---------------- launch ----------------
extern "C" void kernel_launch(void* const* d_in, const int* in_sizes, int n_in,
                              void* d_out, int out_size)
{
    const float* X  = (const float*)d_in[0];
    const float* WQ = (const float*)d_in[1];
    const float* WK = (const float*)d_in[2];
    const float* WV = (const float*)d_in[3];
    const float* WO = (const float*)d_in[4];
    float* out = (float*)d_out;

    conv_x<<<1024, 256>>>((const float4*)X);
    conv_w4<<<1024, 256>>>((const float4*)WQ, (const float4*)WK,
                           (const float4*)WV, (const float4*)WO);

    cudaFuncSetAttribute(gemm_h, cudaFuncAttributeMaxDynamicSharedMemorySize, GSM3);
    cudaFuncSetAttribute(attn_h, cudaFuncAttributeMaxDynamicSharedMemorySize, ATT_SMEM);

    dim3 gqkv(D_MODEL / 256, MTOT / 128, 3);   // (4, 64, 3)
    gemm_h<<<gqkv, 256, GSM3>>>(nullptr, -1);  // Q, K, V in one launch

    dim3 ag(SEQ / 128, BATCH * NHEAD);         // (16, 64)
    attn_h<<<ag, 256, ATT_SMEM>>>();

    dim3 go(D_MODEL / 256, MTOT / 128, 1);     // (4, 64)
    gemm_h<<<go, 256, GSM3>>>(out, 3);         // output projection
}

// round 14
// speedup vs baseline: 1.1671x; 1.1671x over previous
#include <cuda_runtime.h>
#include <cuda_fp16.h>
#include <stdint.h>

#define D_MODEL 1024
#define NHEAD   16
#define DH      64
#define SEQ     2048
#define BATCH   4
#define MTOT    8192
#define KE      2048
#define QSCALE  0.1803368801111244f   /* 0.125 * log2(e) */

// ---------------- scratch globals (no allocation) ----------------
__device__ __half g_Xe[(size_t)MTOT*KE];                 // X hi|lo
__device__ __half g_Te[(size_t)MTOT*KE];                 // attn out hi|lo
__device__ __half g_W[4][(size_t)D_MODEL*D_MODEL];       // weights fp16
__device__ __half g_Qh[(size_t)BATCH*NHEAD*SEQ*DH];      // [B,H,S,64] (pre-scaled)
__device__ __half g_Kh[(size_t)BATCH*NHEAD*SEQ*DH];
__device__ __half g_Vh[(size_t)BATCH*NHEAD*SEQ*DH];

// ---------------- helpers ----------------
__device__ __forceinline__ uint32_t smem_u32(const void* p) {
    uint32_t a;
    asm("{ .reg .u64 t; cvta.to.shared.u64 t, %1; cvt.u32.u64 %0, t; }" : "=r"(a) : "l"(p));
    return a;
}
__device__ __forceinline__ void cp16(uint32_t s, const void* g) {
    asm volatile("cp.async.cg.shared.global [%0], [%1], 16;" :: "r"(s), "l"(g));
}
#define CP_COMMIT() asm volatile("cp.async.commit_group;" ::: "memory")
#define CP_WAIT(n)  asm volatile("cp.async.wait_group %0;" :: "n"(n) : "memory")

__device__ __forceinline__ void ldsm(uint32_t& r0, uint32_t& r1, uint32_t& r2, uint32_t& r3, uint32_t a) {
    asm volatile("ldmatrix.sync.aligned.m8n8.x4.shared.b16 {%0,%1,%2,%3}, [%4];"
                 : "=r"(r0), "=r"(r1), "=r"(r2), "=r"(r3) : "r"(a));
}
__device__ __forceinline__ void ldsmT(uint32_t& r0, uint32_t& r1, uint32_t& r2, uint32_t& r3, uint32_t a) {
    asm volatile("ldmatrix.sync.aligned.m8n8.x4.trans.shared.b16 {%0,%1,%2,%3}, [%4];"
                 : "=r"(r0), "=r"(r1), "=r"(r2), "=r"(r3) : "r"(a));
}
__device__ __forceinline__ void mma16(float* c, uint32_t a0, uint32_t a1, uint32_t a2, uint32_t a3,
                                      uint32_t b0, uint32_t b1) {
    asm volatile("mma.sync.aligned.m16n8k16.row.col.f32.f16.f16.f32 "
                 "{%0,%1,%2,%3}, {%4,%5,%6,%7}, {%8,%9}, {%0,%1,%2,%3};"
                 : "+f"(c[0]), "+f"(c[1]), "+f"(c[2]), "+f"(c[3])
                 : "r"(a0), "r"(a1), "r"(a2), "r"(a3), "r"(b0), "r"(b1));
}
__device__ __forceinline__ float ex2f(float x) {
    float y;
    asm("ex2.approx.ftz.f32 %0, %1;" : "=f"(y) : "f"(x));
    return y;
}
#define SWZ(x) ((uint32_t)(x) ^ ((((uint32_t)(x)) >> 3) & 0x70))

__device__ __forceinline__ uint32_t packh2(float a, float b) {
    __half2 h = __floats2half2_rn(a, b);
    return *reinterpret_cast<uint32_t*>(&h);
}

// ---------------- converters (vectorized) ----------------
__global__ void conv_x(const float4* __restrict__ s) {
    const int N4 = MTOT * D_MODEL / 4;
    for (int i = blockIdx.x * blockDim.x + threadIdx.x; i < N4; i += gridDim.x * blockDim.x) {
        float4 v = s[i];
        int e = i * 4, r = e >> 10, c = e & 1023;
        __half2 h0 = __floats2half2_rn(v.x, v.y);
        __half2 h1 = __floats2half2_rn(v.z, v.w);
        __half2 l0 = __floats2half2_rn(v.x - __half2float(__low2half(h0)),
                                       v.y - __half2float(__high2half(h0)));
        __half2 l1 = __floats2half2_rn(v.z - __half2float(__low2half(h1)),
                                       v.w - __half2float(__high2half(h1)));
        __half* base = g_Xe + (size_t)r * KE + c;
        *(__half2*)(base)        = h0;
        *(__half2*)(base + 2)    = h1;
        *(__half2*)(base + 1024) = l0;
        *(__half2*)(base + 1026) = l1;
    }
}
__global__ void conv_w4(const float4* __restrict__ w0, const float4* __restrict__ w1,
                        const float4* __restrict__ w2, const float4* __restrict__ w3) {
    const int N4 = D_MODEL * D_MODEL / 4;
    for (int i = blockIdx.x * blockDim.x + threadIdx.x; i < 4 * N4; i += gridDim.x * blockDim.x) {
        int m = i >> 18, idx = i & (N4 - 1);
        const float4* s = (m == 0) ? w0 : (m == 1) ? w1 : (m == 2) ? w2 : w3;
        float4 v = s[idx];
        *(__half2*)(g_W[m] + idx * 4)     = __floats2half2_rn(v.x, v.y);
        *(__half2*)(g_W[m] + idx * 4 + 2) = __floats2half2_rn(v.z, v.w);
    }
}

// ---------------- 2-pass fp16 GEMM: C = (Ah+Al) * W^T (R10 winner config) ----------------
// 128x128 block tile, 4 warps (2x2) of 64x64; 16 K-chunks of 64.
// stage = Ah(16K)|Al(16K)|B(16K) = 48KB, double buffered -> 2 CTAs/SM.
// mode_base < 0: mode = blockIdx.z (0/1/2 -> Qh/Kh/Vh); mode 0 pre-scales by QSCALE.
#define GST 49152
__global__ __launch_bounds__(128) void gemm_h(float* __restrict__ outp, int mode_base)
{
    extern __shared__ char smem[];
    uint32_t sb = smem_u32(smem);
    int mode = (mode_base < 0) ? (int)blockIdx.z : mode_base;
    int tid = threadIdx.x, lid = tid & 31, wid = tid >> 5;
    int wm = wid >> 1, wn = wid & 1;
    int m0 = blockIdx.y * 128, n0 = blockIdx.x * 128;

    const __half* A = (mode == 3) ? g_Te : g_Xe;
    const char* Ab = (const char*)(A + (size_t)m0 * KE);
    const char* Bb = (const char*)(g_W[mode] + (size_t)n0 * D_MODEL);

    float acc[4][8][4];
#pragma unroll
    for (int mt = 0; mt < 4; ++mt)
#pragma unroll
        for (int j = 0; j < 8; ++j)
#pragma unroll
            for (int v = 0; v < 4; ++v) acc[mt][j][v] = 0.f;

    auto LD = [&](int c, uint32_t st) {
#pragma unroll
        for (int t = 0; t < 8; ++t) {
            int idx = tid + t * 128, row = idx >> 3, cc = (idx & 7) * 16;
            uint32_t so = SWZ(row * 128 + cc);
            cp16(st + so,         Ab + (size_t)row * 4096 + c * 128 + cc);
            cp16(st + 16384 + so, Ab + (size_t)row * 4096 + 2048 + c * 128 + cc);
            cp16(st + 32768 + so, Bb + (size_t)row * 2048 + c * 128 + cc);
        }
    };

    LD(0, sb); CP_COMMIT();
    for (int i = 0; i < 16; ++i) {
        int cur = i & 1;
        if (i + 1 < 16) { LD(i + 1, sb + (cur ^ 1) * GST); CP_COMMIT(); CP_WAIT(1); }
        else CP_WAIT(0);
        __syncthreads();
        uint32_t st = sb + cur * GST;
#pragma unroll
        for (int ks = 0; ks < 4; ++ks) {
            int kb = ks * 32;
            uint32_t ah[4][4], al[4][4];
#pragma unroll
            for (int mt = 0; mt < 4; ++mt) {
                uint32_t off = SWZ((wm * 64 + mt * 16 + (lid & 15)) * 128 + kb + (lid >> 4) * 16);
                ldsm(ah[mt][0], ah[mt][1], ah[mt][2], ah[mt][3], st + off);
                ldsm(al[mt][0], al[mt][1], al[mt][2], al[mt][3], st + 16384 + off);
            }
#pragma unroll
            for (int ng = 0; ng < 4; ++ng) {
                uint32_t boff = SWZ((wn * 64 + ng * 16 + ((lid >> 4) << 3) + (lid & 7)) * 128
                                    + kb + ((lid >> 3) & 1) * 16);
                uint32_t b0, b1, b2, b3;
                ldsm(b0, b1, b2, b3, st + 32768 + boff);
#pragma unroll
                for (int mt = 0; mt < 4; ++mt) {
                    mma16(acc[mt][ng * 2],     ah[mt][0], ah[mt][1], ah[mt][2], ah[mt][3], b0, b1);
                    mma16(acc[mt][ng * 2 + 1], ah[mt][0], ah[mt][1], ah[mt][2], ah[mt][3], b2, b3);
                    mma16(acc[mt][ng * 2],     al[mt][0], al[mt][1], al[mt][2], al[mt][3], b0, b1);
                    mma16(acc[mt][ng * 2 + 1], al[mt][0], al[mt][1], al[mt][2], al[mt][3], b2, b3);
                }
            }
        }
        __syncthreads();
    }

    float sc = (mode == 0) ? QSCALE : 1.0f;
#pragma unroll
    for (int mt = 0; mt < 4; ++mt)
#pragma unroll
        for (int j = 0; j < 8; ++j) {
            int row = m0 + wm * 64 + mt * 16 + (lid >> 2);
            int col = n0 + wn * 64 + j * 8 + ((lid & 3) << 1);
            if (mode == 3) {
                *(float2*)(outp + (size_t)row * D_MODEL + col)       = make_float2(acc[mt][j][0], acc[mt][j][1]);
                *(float2*)(outp + (size_t)(row + 8) * D_MODEL + col) = make_float2(acc[mt][j][2], acc[mt][j][3]);
            } else {
                __half* dst = (mode == 0) ? g_Qh : (mode == 1) ? g_Kh : g_Vh;
                int h = col >> 6, d = col & 63;
                int b0_ = row >> 11, s0 = row & 2047, r1 = row + 8, b1_ = r1 >> 11, s1 = r1 & 2047;
                *(__half2*)(dst + (((size_t)(b0_ * NHEAD + h) * SEQ + s0)) * DH + d)
                    = __floats2half2_rn(acc[mt][j][0] * sc, acc[mt][j][1] * sc);
                *(__half2*)(dst + (((size_t)(b1_ * NHEAD + h) * SEQ + s1)) * DH + d)
                    = __floats2half2_rn(acc[mt][j][2] * sc, acc[mt][j][3] * sc);
            }
        }
}

// ---------------- fp16 tensor-core flash attention ----------------
// 128 q/block, 8 warps x 16q; 3-stage KV pipeline, ONE sync per 64-key tile.
// Q pre-scaled by 0.125*log2(e); softmax in base-2 via ex2.approx.
#define ATT_SMEM (16384 + 3 * 16384)   // Q 16K | 3 x (K 8K | V 8K)
__global__ __launch_bounds__(256) void attn_h()
{
    extern __shared__ char smem[];
    uint32_t sb = smem_u32(smem);
    uint32_t Qs = sb;
    uint32_t Ks[3] = {sb + 16384, sb + 32768, sb + 49152};
    uint32_t Vs[3] = {sb + 24576, sb + 40960, sb + 57344};

    int tid = threadIdx.x, lid = tid & 31, w = tid >> 5;
    int qb = (int)gridDim.x - 1 - (int)blockIdx.x;   // long blocks first
    int bh = blockIdx.y;

    const char* Qg = (const char*)(g_Qh + ((size_t)bh * SEQ + qb * 128) * DH);
    const char* Kg = (const char*)(g_Kh + (size_t)bh * SEQ * DH);
    const char* Vg = (const char*)(g_Vh + (size_t)bh * SEQ * DH);

    auto loadKV = [&](int kt, int st) {
#pragma unroll
        for (int t = 0; t < 2; ++t) {
            int idx = tid + t * 256, row = idx >> 3, c = (idx & 7) * 16;
            uint32_t so = SWZ(row * 128 + c);
            cp16(Ks[st] + so, Kg + (size_t)(kt * 64 + row) * 128 + c);
            cp16(Vs[st] + so, Vg + (size_t)(kt * 64 + row) * 128 + c);
        }
    };

    int ntiles = 2 * qb + 2;

    // G0: Q + KV0 ; G1: KV1
#pragma unroll
    for (int t = 0; t < 4; ++t) {
        int idx = tid + t * 256, row = idx >> 3, c = (idx & 7) * 16;
        cp16(Qs + SWZ(row * 128 + c), Qg + (size_t)row * 128 + c);
    }
    loadKV(0, 0); CP_COMMIT();
    if (ntiles > 1) loadKV(1, 1);
    CP_COMMIT();
    CP_WAIT(1); __syncthreads();     // G0 (Q + KV0) complete

    uint32_t qf[4][4];
#pragma unroll
    for (int ks = 0; ks < 4; ++ks) {
        uint32_t off = SWZ((w * 16 + (lid & 15)) * 128 + ks * 32 + (lid >> 4) * 16);
        ldsm(qf[ks][0], qf[ks][1], qf[ks][2], qf[ks][3], Qs + off);
    }

    float o[8][4];
#pragma unroll
    for (int j = 0; j < 8; ++j)
#pragma unroll
        for (int v = 0; v < 4; ++v) o[j][v] = 0.f;
    float m0 = -1e30f, m1 = -1e30f, l0 = 0.f, l1 = 0.f;

    int r0 = lid >> 2, c0 = (lid & 3) << 1;
    int qlo = qb * 128 + w * 16;

    for (int kt = 0; kt < ntiles; ++kt) {
        int st = kt % 3;
        if (kt > 0) { CP_WAIT(1); __syncthreads(); }   // KV_kt ready; stage (kt+2)%3 free
        if (kt + 2 < ntiles) loadKV(kt + 2, (kt + 2) % 3);
        CP_COMMIT();                                    // unconditional: keeps group count aligned

        if (kt * 64 <= qlo + 15) {
            float s[8][4];
#pragma unroll
            for (int j = 0; j < 8; ++j)
#pragma unroll
                for (int v = 0; v < 4; ++v) s[j][v] = 0.f;
#pragma unroll
            for (int ks = 0; ks < 4; ++ks) {
                int kb = ks * 32;
#pragma unroll
                for (int ng = 0; ng < 4; ++ng) {
                    uint32_t boff = SWZ((ng * 16 + ((lid >> 4) << 3) + (lid & 7)) * 128
                                        + kb + ((lid >> 3) & 1) * 16);
                    uint32_t b0, b1, b2, b3;
                    ldsm(b0, b1, b2, b3, Ks[st] + boff);
                    mma16(s[ng * 2],     qf[ks][0], qf[ks][1], qf[ks][2], qf[ks][3], b0, b1);
                    mma16(s[ng * 2 + 1], qf[ks][0], qf[ks][1], qf[ks][2], qf[ks][3], b2, b3);
                }
            }
            if (kt * 64 + 63 > qlo) {   // diagonal: apply causal mask
#pragma unroll
                for (int j = 0; j < 8; ++j)
#pragma unroll
                    for (int v = 0; v < 4; ++v) {
                        int key = kt * 64 + j * 8 + c0 + (v & 1);
                        int q = qlo + r0 + ((v >> 1) << 3);
                        if (key > q) s[j][v] = -1e30f;
                    }
            }
            float mt0 = -1e30f, mt1 = -1e30f;
#pragma unroll
            for (int j = 0; j < 8; ++j) {
                mt0 = fmaxf(mt0, fmaxf(s[j][0], s[j][1]));
                mt1 = fmaxf(mt1, fmaxf(s[j][2], s[j][3]));
            }
            mt0 = fmaxf(mt0, __shfl_xor_sync(0xffffffffu, mt0, 1));
            mt0 = fmaxf(mt0, __shfl_xor_sync(0xffffffffu, mt0, 2));
            mt1 = fmaxf(mt1, __shfl_xor_sync(0xffffffffu, mt1, 1));
            mt1 = fmaxf(mt1, __shfl_xor_sync(0xffffffffu, mt1, 2));
            float mn0 = fmaxf(m0, mt0), mn1 = fmaxf(m1, mt1);
            float a0 = ex2f(m0 - mn0), a1 = ex2f(m1 - mn1);
            m0 = mn0; m1 = mn1;
            float ls0 = 0.f, ls1 = 0.f;
            uint32_t pa[8], pb[8];
#pragma unroll
            for (int j = 0; j < 8; ++j) {
                float p00 = ex2f(s[j][0] - mn0), p01 = ex2f(s[j][1] - mn0);
                float p10 = ex2f(s[j][2] - mn1), p11 = ex2f(s[j][3] - mn1);
                ls0 += p00 + p01; ls1 += p10 + p11;
                pa[j] = packh2(p00, p01);
                pb[j] = packh2(p10, p11);
            }
            ls0 += __shfl_xor_sync(0xffffffffu, ls0, 1);
            ls0 += __shfl_xor_sync(0xffffffffu, ls0, 2);
            ls1 += __shfl_xor_sync(0xffffffffu, ls1, 1);
            ls1 += __shfl_xor_sync(0xffffffffu, ls1, 2);
            l0 = l0 * a0 + ls0; l1 = l1 * a1 + ls1;
#pragma unroll
            for (int j = 0; j < 8; ++j) {
                o[j][0] *= a0; o[j][1] *= a0; o[j][2] *= a1; o[j][3] *= a1;
            }
#pragma unroll
            for (int ks2 = 0; ks2 < 4; ++ks2) {
                uint32_t A0 = pa[2 * ks2], A1 = pb[2 * ks2], A2 = pa[2 * ks2 + 1], A3 = pb[2 * ks2 + 1];
#pragma unroll
                for (int ng = 0; ng < 4; ++ng) {
                    uint32_t voff = SWZ((ks2 * 16 + ((lid >> 3) & 1) * 8 + (lid & 7)) * 128
                                        + ng * 32 + (lid >> 4) * 16);
                    uint32_t b0, b1, b2, b3;
                    ldsmT(b0, b1, b2, b3, Vs[st] + voff);
                    mma16(o[ng * 2],     A0, A1, A2, A3, b0, b1);
                    mma16(o[ng * 2 + 1], A0, A1, A2, A3, b2, b3);
                }
            }
        }
    }

    float il0 = 1.f / l0, il1 = 1.f / l1;
    int b = bh >> 4, h = bh & 15;
    size_t t0 = (size_t)b * SEQ + qb * 128 + w * 16 + r0;
    size_t t1 = t0 + 8;
#pragma unroll
    for (int j = 0; j < 8; ++j) {
        int d = h * 64 + j * 8 + c0;
        float x0 = o[j][0] * il0, x1 = o[j][1] * il0;
        float y0 = o[j][2] * il1, y1 = o[j][3] * il1;
        __half h0 = __float2half_rn(x0), h1 = __float2half_rn(x1);
        __half g0 = __float2half_rn(y0), g1 = __float2half_rn(y1);
        *(__half2*)&g_Te[t0 * KE + d] = __halves2half2(h0, h1);
        *(__half2*)&g_Te[t1 * KE + d] = __halves2half2(g0, g1);
        *(__half2*)&g_Te[t0 * KE + 1024 + d] =
            __floats2half2_rn(x0 - __half2float(h0), x1 - __half2float(h1));
        *(__half2*)&g_Te[t1 * KE + 1024 + d] =
            __floats2half2_rn(y0 - __half2float(g0), y1 - __half2float(g1));
    }
}

// ---------------- launch ----------------
extern "C" void kernel_launch(void* const* d_in, const int* in_sizes, int n_in,
                              void* d_out, int out_size)
{
    const float* X  = (const float*)d_in[0];
    const float* WQ = (const float*)d_in[1];
    const float* WK = (const float*)d_in[2];
    const float* WV = (const float*)d_in[3];
    const float* WO = (const float*)d_in[4];
    float* out = (float*)d_out;

    conv_x<<<1024, 256>>>((const float4*)X);
    conv_w4<<<1024, 256>>>((const float4*)WQ, (const float4*)WK,
                           (const float4*)WV, (const float4*)WO);

    cudaFuncSetAttribute(gemm_h, cudaFuncAttributeMaxDynamicSharedMemorySize, 2 * GST);
    cudaFuncSetAttribute(attn_h, cudaFuncAttributeMaxDynamicSharedMemorySize, ATT_SMEM);

    dim3 gqkv(D_MODEL / 128, MTOT / 128, 3);   // (8, 64, 3)
    gemm_h<<<gqkv, 128, 2 * GST>>>(nullptr, -1);  // Q, K, V in one launch

    dim3 ag(SEQ / 128, BATCH * NHEAD);         // (16, 64)
    attn_h<<<ag, 256, ATT_SMEM>>>();

    dim3 go(D_MODEL / 128, MTOT / 128, 1);     // (8, 64)
    gemm_h<<<go, 128, 2 * GST>>>(out, 3);      // output projection
}